// round 14
// baseline (speedup 1.0000x reference)
#include <cuda_runtime.h>
#include <cuda_fp16.h>
#include <cstdint>

#define HEADS 12
#define HEAD_S 64
#define BATCH 32
#define SEQ 512
#define DIM 768
#define NPROJ (HEADS * HEAD_S * 2)   // 1536
#define MROWS (BATCH * SEQ)          // 16384
#define NEGC 1000000000000.0f
#define NEG8 (NEGC * 0.125f)

// -------- scratch (device globals; no allocation allowed) --------
__device__ __half g_x[(size_t)MROWS * DIM];
__device__ __half g_Wt[NPROJ * DIM];
__device__ __half g_Q[(size_t)BATCH * HEADS * SEQ * HEAD_S];
__device__ __half g_K[(size_t)BATCH * HEADS * SEQ * HEAD_S];
__device__ float g_sin[SEQ * 32];
__device__ float g_cos[SEQ * 32];

// -------- helpers --------
#define SW128(o) ((o) ^ (((o) >> 3) & 0x70))    // 128B-row xor swizzle

__device__ __forceinline__ uint32_t saddr(const void* p) {
    return (uint32_t)__cvta_generic_to_shared(p);
}
__device__ __forceinline__ unsigned pkh(float a, float b) {
    __half2 h = __floats2half2_rn(a, b);
    return *reinterpret_cast<unsigned*>(&h);
}
__device__ __forceinline__ void cpasync16s(uint32_t s, const void* gmem) {
    asm volatile("cp.async.cg.shared.global [%0], [%1], 16;" :: "r"(s), "l"(gmem));
}
#define CP_COMMIT asm volatile("cp.async.commit_group;")
#define CP_WAIT(n) asm volatile("cp.async.wait_group %0;" :: "n"(n))

__device__ __forceinline__ void ldmx4(unsigned* r, uint32_t addr) {
    asm volatile("ldmatrix.sync.aligned.m8n8.x4.shared.b16 {%0,%1,%2,%3},[%4];"
                 : "=r"(r[0]), "=r"(r[1]), "=r"(r[2]), "=r"(r[3]) : "r"(addr));
}
// f16-acc MMA
__device__ __forceinline__ void mmaf16(unsigned* c, const unsigned* a, const unsigned* b) {
    asm volatile(
        "mma.sync.aligned.m16n8k16.row.col.f16.f16.f16.f16 "
        "{%0,%1},{%2,%3,%4,%5},{%6,%7},{%0,%1};"
        : "+r"(c[0]), "+r"(c[1])
        : "r"(a[0]), "r"(a[1]), "r"(a[2]), "r"(a[3]), "r"(b[0]), "r"(b[1]));
}
// f32-acc MMA (f16 inputs)
__device__ __forceinline__ void mmaf32(float* c, const unsigned* a, const unsigned* b) {
    asm volatile(
        "mma.sync.aligned.m16n8k16.row.col.f32.f16.f16.f32 "
        "{%0,%1,%2,%3},{%4,%5,%6,%7},{%8,%9},{%0,%1,%2,%3};"
        : "+f"(c[0]), "+f"(c[1]), "+f"(c[2]), "+f"(c[3])
        : "r"(a[0]), "r"(a[1]), "r"(a[2]), "r"(a[3]), "r"(b[0]), "r"(b[1]));
}

// =============================================================
// Fused prep: x->f16 (0..6143), W transpose->f16 (6144..7295), rope (7296..7359)
// =============================================================
#define PREP_XBLK 6144
#define PREP_WBLK 1152
#define PREP_RBLK 64
__global__ __launch_bounds__(256) void prep(const float* __restrict__ x,
                                            const float* __restrict__ W) {
    __shared__ float t[32][33];
    int bid = blockIdx.x, tid = threadIdx.x;
    if (bid < PREP_XBLK) {
        size_t i = ((size_t)bid * 256 + tid) * 8;
        const float4* p = (const float4*)(x + i);
        float4 u = p[0], v = p[1];
        uint4 w;
        w.x = pkh(u.x, u.y); w.y = pkh(u.z, u.w);
        w.z = pkh(v.x, v.y); w.w = pkh(v.z, v.w);
        *(uint4*)&g_x[i] = w;
    } else if (bid < PREP_XBLK + PREP_WBLK) {
        int tile = bid - PREP_XBLK;
        int nt = (tile % 48) * 32, kt = (tile / 48) * 32;
        int tx = tid & 31, ty = tid >> 5;
        for (int i2 = ty; i2 < 32; i2 += 8)
            t[i2][tx] = W[(size_t)(kt + i2) * NPROJ + nt + tx];
        __syncthreads();
        for (int i2 = ty; i2 < 32; i2 += 8)
            g_Wt[(size_t)(nt + i2) * DIM + kt + tx] = __float2half(t[tx][i2]);
    } else {
        int idx = (bid - PREP_XBLK - PREP_WBLK) * 256 + tid;  // < 16384
        int l = idx >> 5, i2 = idx & 31;
        float freq = powf(10000.0f, -(2.0f * (float)i2) / 64.0f);
        float ang = (float)l * freq;
        g_sin[idx] = sinf(ang);
        g_cos[idx] = cosf(ang);
    }
}

// =============================================================
// Stage 1 (R13 winner): 128 threads, CTA tile 128x128, warp 64x64,
// BK=64, 2-stage swizzled ring, f16 acc, ks-double-buffered frags.
// mblk = mblk0 + blockIdx.y (batch-half split)
// =============================================================
#define S1_TILE 16384
#define S1_STG  (2 * S1_TILE)
#define S1_SMEM (2 * S1_STG)                // 65536 B

__global__ __launch_bounds__(128, 3) void stage1(const float* __restrict__ bias,
                                                 int mblk0) {
    extern __shared__ char sm1[];
    __shared__ float sBias[128];
    uint32_t base = saddr(sm1);

    int tid = threadIdx.x, warp = tid >> 5, lane = tid & 31;
    int head = blockIdx.x, mblk = mblk0 + blockIdx.y;
    int wm = (warp >> 1) * 64;
    int wn = (warp & 1) * 64;

    if (tid < 128) sBias[tid] = bias[head * 128 + tid];

    const __half* xb = g_x + (size_t)mblk * 128 * DIM;
    const __half* wb = g_Wt + (size_t)head * 128 * DIM;
    int lrow = tid >> 3;
    int lch = (tid & 7) * 16;

    auto issue = [&](int buf, int t) {
        uint32_t ab = base + buf * S1_STG;
        uint32_t bb = ab + S1_TILE;
        const __half* xp = xb + t * 64 + (tid & 7) * 8;
        const __half* wp = wb + t * 64 + (tid & 7) * 8;
#pragma unroll
        for (int it = 0; it < 8; it++) {
            int row = it * 16 + lrow;
            uint32_t o = row * 128 + lch;
            uint32_t so = SW128(o);
            cpasync16s(ab + so, xp + (size_t)row * DIM);
            cpasync16s(bb + so, wp + (size_t)row * DIM);
        }
        CP_COMMIT;
    };

    uint32_t aOff[4], bOff[4], aXor[4], bXor[4];
#pragma unroll
    for (int mt = 0; mt < 4; mt++) {
        int r = wm + mt * 16 + (lane & 7) + ((lane >> 3) & 1) * 8;
        aXor[mt] = (r & 7) * 16;
        aOff[mt] = r * 128;
    }
#pragma unroll
    for (int np = 0; np < 4; np++) {
        int g = lane >> 3;
        int r = wn + np * 16 + (lane & 7) + (g >> 1) * 8;
        bXor[np] = (r & 7) * 16;
        bOff[np] = r * 128;
    }
    uint32_t aC0 = (lane >> 4) * 16;
    uint32_t bC0 = ((lane >> 3) & 1) * 16;

    unsigned acc[4][8][2];
#pragma unroll
    for (int a = 0; a < 4; a++)
#pragma unroll
        for (int b = 0; b < 8; b++) { acc[a][b][0] = 0u; acc[a][b][1] = 0u; }

    issue(0, 0);
    issue(1, 1);

    unsigned af[2][4][4], bf[2][4][4];

    const int NK = DIM / 64;   // 12
    for (int i = 0; i < NK; i++) {
        if (i == NK - 1) { CP_WAIT(0); } else { CP_WAIT(1); }
        __syncthreads();
        uint32_t ab = base + (i & 1) * S1_STG;
        uint32_t bb = ab + S1_TILE;

#pragma unroll
        for (int mt = 0; mt < 4; mt++)
            ldmx4(af[0][mt], ab + aOff[mt] + (aC0 ^ aXor[mt]));
#pragma unroll
        for (int np = 0; np < 4; np++)
            ldmx4(bf[0][np], bb + bOff[np] + (bC0 ^ bXor[np]));

#pragma unroll
        for (int ks = 0; ks < 4; ks++) {
            int cur = ks & 1, nxt = cur ^ 1;
            if (ks < 3) {
                uint32_t kc = (ks + 1) * 32;
#pragma unroll
                for (int mt = 0; mt < 4; mt++)
                    ldmx4(af[nxt][mt], ab + aOff[mt] + ((kc + aC0) ^ aXor[mt]));
#pragma unroll
                for (int np = 0; np < 4; np++)
                    ldmx4(bf[nxt][np], bb + bOff[np] + ((kc + bC0) ^ bXor[np]));
            }
#pragma unroll
            for (int mt = 0; mt < 4; mt++)
#pragma unroll
                for (int np = 0; np < 4; np++) {
                    mmaf16(acc[mt][2 * np],     af[cur][mt], &bf[cur][np][0]);
                    mmaf16(acc[mt][2 * np + 1], af[cur][mt], &bf[cur][np][2]);
                }
        }
        __syncthreads();
        if (i + 2 < NK) issue(i & 1, i + 2);
    }

    int gmb = mblk * 128;
#pragma unroll
    for (int mt = 0; mt < 4; mt++) {
#pragma unroll
        for (int nt = 0; nt < 8; nt++) {
            int ncol = wn + nt * 8 + 2 * (lane & 3);
            int rch = ncol & 63;
            int i = rch >> 1;
            bool isQ = ncol < 64;
            float b0 = sBias[ncol], b1 = sBias[ncol + 1];
#pragma unroll
            for (int rr = 0; rr < 2; rr++) {
                int row = wm + mt * 16 + (lane >> 2) + rr * 8;
                int gm = gmb + row;
                int bb2 = gm >> 9;
                int l = gm & 511;
                __half2 h = *reinterpret_cast<__half2*>(&acc[mt][nt][rr]);
                float v0 = __low2float(h) + b0;
                float v1 = __high2float(h) + b1;
                float sn = g_sin[l * 32 + i], cs = g_cos[l * 32 + i];
                float o0 = v0 * cs - v1 * sn;
                float o1 = v1 * cs + v0 * sn;
                size_t off = (((size_t)(bb2 * HEADS + head) * SEQ + l) * HEAD_S + rch);
                __half* dst = (isQ ? g_Q : g_K) + off;
                *(__half2*)dst = __floats2half2_rn(o0, o1);
            }
        }
    }
}

// =============================================================
// Stage 2 (R11 winner body): per (b,h): full 128x512 strip per CTA.
// bh = bh0 + blockIdx.y (batch-half split)
// =============================================================
#define S2_Q_OFF 0
#define S2_K_OFF (128 * 72 * 2)
#define S2_RS_OFF (S2_K_OFF + 512 * 72 * 2)
#define S2_RA_OFF (S2_RS_OFF + 128 * 4)
#define S2_CM_OFF (S2_RA_OFF + 128 * 4)
#define S2_CA_OFF (S2_CM_OFF + 512 * 4)
#define S2_SMEM   (S2_CA_OFF + 512 * 4)     // 97280

__global__ __launch_bounds__(256, 2) void stage2(const float* __restrict__ mask,
                                                 float* __restrict__ out, int bh0) {
    extern __shared__ char sm2[];
    __half* sQ = (__half*)(sm2 + S2_Q_OFF);
    __half* sK = (__half*)(sm2 + S2_K_OFF);
    float* s_rs = (float*)(sm2 + S2_RS_OFF);
    float* s_ra = (float*)(sm2 + S2_RA_OFF);
    float* s_cm = (float*)(sm2 + S2_CM_OFF);
    float* s_ca = (float*)(sm2 + S2_CA_OFF);

    int mtb = blockIdx.x, bh = bh0 + blockIdx.y;
    int b = bh / HEADS;
    int tid = threadIdx.x, warp = tid >> 5, lane = tid & 31;
    int wm = (warp >> 1) * 32;
    int wn = (warp & 1) * 64;

    const __half* Qb = g_Q + (size_t)bh * SEQ * HEAD_S + (size_t)mtb * 128 * HEAD_S;
    const __half* Kb = g_K + (size_t)bh * SEQ * HEAD_S;

    int lrow = tid >> 3, lkk = (tid & 7) * 8;
#pragma unroll
    for (int it = 0; it < 4; it++) {
        int row = it * 32 + lrow;
        cpasync16s(saddr(&sQ[row * 72 + lkk]), Qb + (size_t)row * HEAD_S + lkk);
    }
#pragma unroll
    for (int it = 0; it < 16; it++) {
        int row = it * 32 + lrow;
        cpasync16s(saddr(&sK[row * 72 + lkk]), Kb + (size_t)row * HEAD_S + lkk);
    }
    CP_COMMIT;

    const float* mrow = mask + (size_t)b * SEQ;
    if (tid < 128) {
        float m2 = mrow[mtb * 128 + tid];
        s_rs[tid] = m2 * 0.125f;
        s_ra[tid] = (1.0f - m2) * (-NEG8);
    }
#pragma unroll
    for (int q = 0; q < 2; q++) {
        int cidx = q * 256 + tid;
        float m3 = mrow[cidx];
        s_cm[cidx] = m3;
        s_ca[cidx] = (1.0f - m3) * (-NEG8);
    }
    CP_WAIT(0);
    __syncthreads();

    float* ob = out + (size_t)bh * (SEQ * SEQ);

    for (int ntb = 0; ntb < 4; ntb++) {
        float acc[2][8][4];
#pragma unroll
        for (int a = 0; a < 2; a++)
#pragma unroll
            for (int c = 0; c < 8; c++)
#pragma unroll
                for (int d = 0; d < 4; d++) acc[a][c][d] = 0.0f;

#pragma unroll
        for (int ks = 0; ks < 4; ks++) {
            int kb = ks * 16;
            unsigned a[2][4], bf[4][4];
#pragma unroll
            for (int mt = 0; mt < 2; mt++) {
                int r = wm + mt * 16 + (lane & 7) + ((lane >> 3) & 1) * 8;
                int c = kb + (lane >> 4) * 8;
                ldmx4(a[mt], saddr(&sQ[r * 72 + c]));
            }
#pragma unroll
            for (int np = 0; np < 4; np++) {
                int g = lane >> 3;
                int r = ntb * 128 + wn + np * 16 + (lane & 7) + (g >> 1) * 8;
                int c = kb + (g & 1) * 8;
                ldmx4(bf[np], saddr(&sK[r * 72 + c]));
            }
#pragma unroll
            for (int mt = 0; mt < 2; mt++)
#pragma unroll
                for (int np = 0; np < 4; np++) {
                    mmaf32(acc[mt][2 * np], a[mt], &bf[np][0]);
                    mmaf32(acc[mt][2 * np + 1], a[mt], &bf[np][2]);
                }
        }

#pragma unroll
        for (int mt = 0; mt < 2; mt++) {
#pragma unroll
            for (int rr = 0; rr < 2; rr++) {
                int rl = wm + mt * 16 + (lane >> 2) + rr * 8;
                int row = mtb * 128 + rl;
                float rs = s_rs[rl], ra = s_ra[rl];
#pragma unroll
                for (int nt = 0; nt < 8; nt++) {
                    int col = ntb * 128 + wn + nt * 8 + 2 * (lane & 3);
                    int cl = col & 511;
                    float v0 = (acc[mt][nt][rr * 2 + 0] * rs + ra) * s_cm[cl] + s_ca[cl];
                    float v1 = (acc[mt][nt][rr * 2 + 1] * rs + ra) * s_cm[cl + 1] + s_ca[cl + 1];
                    if (row > col)     v0 -= NEG8;
                    if (row > col + 1) v1 -= NEG8;
                    __stcs((float2*)&ob[(size_t)row * SEQ + col], make_float2(v0, v1));
                }
            }
        }
    }
}

extern "C" void kernel_launch(void* const* d_in, const int* in_sizes, int n_in,
                              void* d_out, int out_size) {
    const float* x    = (const float*)d_in[0];
    const float* mask = (const float*)d_in[1];
    const float* W    = (const float*)d_in[2];
    const float* bias = (const float*)d_in[3];
    float* out = (float*)d_out;

    static cudaStream_t s2s = nullptr;
    static cudaEvent_t ev1, ev2, evJoin;
    static bool init_done = false;
    if (!init_done) {
        cudaFuncSetAttribute(stage1, cudaFuncAttributeMaxDynamicSharedMemorySize, S1_SMEM);
        cudaFuncSetAttribute(stage2, cudaFuncAttributeMaxDynamicSharedMemorySize, S2_SMEM);
        cudaStreamCreateWithFlags(&s2s, cudaStreamNonBlocking);
        cudaEventCreateWithFlags(&ev1, cudaEventDisableTiming);
        cudaEventCreateWithFlags(&ev2, cudaEventDisableTiming);
        cudaEventCreateWithFlags(&evJoin, cudaEventDisableTiming);
        init_done = true;
    }

    prep<<<PREP_XBLK + PREP_WBLK + PREP_RBLK, 256>>>(x, W);

    // stage1 first half: batches 0..15 (mblk 0..63)
    stage1<<<dim3(HEADS, 64), 128, S1_SMEM>>>(bias, 0);
    cudaEventRecord(ev1, 0);

    // stage1 second half on main stream; stage2 first half concurrently
    stage1<<<dim3(HEADS, 64), 128, S1_SMEM>>>(bias, 64);
    cudaEventRecord(ev2, 0);

    cudaStreamWaitEvent(s2s, ev1, 0);
    stage2<<<dim3(4, 192), 256, S2_SMEM, s2s>>>(mask, out, 0);     // batches 0..15

    cudaStreamWaitEvent(s2s, ev2, 0);
    stage2<<<dim3(4, 192), 256, S2_SMEM, s2s>>>(mask, out, 192);   // batches 16..31

    cudaEventRecord(evJoin, s2s);
    cudaStreamWaitEvent(0, evJoin, 0);
}

// round 15
// speedup vs baseline: 1.1330x; 1.1330x over previous
#include <cuda_runtime.h>
#include <cuda_fp16.h>
#include <cstdint>

#define HEADS 12
#define HEAD_S 64
#define BATCH 32
#define SEQ 512
#define DIM 768
#define NPROJ (HEADS * HEAD_S * 2)   // 1536
#define MROWS (BATCH * SEQ)          // 16384
#define NEGC 1000000000000.0f
#define NEG8 (NEGC * 0.125f)

// -------- scratch (device globals; no allocation allowed) --------
__device__ __half g_x[(size_t)MROWS * DIM];
__device__ __half g_Wt[NPROJ * DIM];
__device__ __half g_Q[(size_t)BATCH * HEADS * SEQ * HEAD_S];
__device__ __half g_K[(size_t)BATCH * HEADS * SEQ * HEAD_S];
__device__ float g_sin[SEQ * 32];
__device__ float g_cos[SEQ * 32];

// -------- helpers --------
#define SW128(o) ((o) ^ (((o) >> 3) & 0x70))    // 128B-row xor swizzle

__device__ __forceinline__ uint32_t saddr(const void* p) {
    return (uint32_t)__cvta_generic_to_shared(p);
}
__device__ __forceinline__ unsigned pkh(float a, float b) {
    __half2 h = __floats2half2_rn(a, b);
    return *reinterpret_cast<unsigned*>(&h);
}
__device__ __forceinline__ void cpasync16s(uint32_t s, const void* gmem) {
    asm volatile("cp.async.cg.shared.global [%0], [%1], 16;" :: "r"(s), "l"(gmem));
}
#define CP_COMMIT asm volatile("cp.async.commit_group;")
#define CP_WAIT(n) asm volatile("cp.async.wait_group %0;" :: "n"(n))

__device__ __forceinline__ void ldmx4(unsigned* r, uint32_t addr) {
    asm volatile("ldmatrix.sync.aligned.m8n8.x4.shared.b16 {%0,%1,%2,%3},[%4];"
                 : "=r"(r[0]), "=r"(r[1]), "=r"(r[2]), "=r"(r[3]) : "r"(addr));
}
// f16-acc MMA
__device__ __forceinline__ void mmaf16(unsigned* c, const unsigned* a, const unsigned* b) {
    asm volatile(
        "mma.sync.aligned.m16n8k16.row.col.f16.f16.f16.f16 "
        "{%0,%1},{%2,%3,%4,%5},{%6,%7},{%0,%1};"
        : "+r"(c[0]), "+r"(c[1])
        : "r"(a[0]), "r"(a[1]), "r"(a[2]), "r"(a[3]), "r"(b[0]), "r"(b[1]));
}
// f32-acc MMA (f16 inputs)
__device__ __forceinline__ void mmaf32(float* c, const unsigned* a, const unsigned* b) {
    asm volatile(
        "mma.sync.aligned.m16n8k16.row.col.f32.f16.f16.f32 "
        "{%0,%1,%2,%3},{%4,%5,%6,%7},{%8,%9},{%0,%1,%2,%3};"
        : "+f"(c[0]), "+f"(c[1]), "+f"(c[2]), "+f"(c[3])
        : "r"(a[0]), "r"(a[1]), "r"(a[2]), "r"(a[3]), "r"(b[0]), "r"(b[1]));
}

// =============================================================
// Fused prep: x->f16 (0..6143), W transpose->f16 (6144..7295), rope (7296..7359)
// =============================================================
#define PREP_XBLK 6144
#define PREP_WBLK 1152
#define PREP_RBLK 64
__global__ __launch_bounds__(256) void prep(const float* __restrict__ x,
                                            const float* __restrict__ W) {
    __shared__ float t[32][33];
    int bid = blockIdx.x, tid = threadIdx.x;
    if (bid < PREP_XBLK) {
        size_t i = ((size_t)bid * 256 + tid) * 8;
        const float4* p = (const float4*)(x + i);
        float4 u = p[0], v = p[1];
        uint4 w;
        w.x = pkh(u.x, u.y); w.y = pkh(u.z, u.w);
        w.z = pkh(v.x, v.y); w.w = pkh(v.z, v.w);
        *(uint4*)&g_x[i] = w;
    } else if (bid < PREP_XBLK + PREP_WBLK) {
        int tile = bid - PREP_XBLK;
        int nt = (tile % 48) * 32, kt = (tile / 48) * 32;
        int tx = tid & 31, ty = tid >> 5;
        for (int i2 = ty; i2 < 32; i2 += 8)
            t[i2][tx] = W[(size_t)(kt + i2) * NPROJ + nt + tx];
        __syncthreads();
        for (int i2 = ty; i2 < 32; i2 += 8)
            g_Wt[(size_t)(nt + i2) * DIM + kt + tx] = __float2half(t[tx][i2]);
    } else {
        int idx = (bid - PREP_XBLK - PREP_WBLK) * 256 + tid;  // < 16384
        int l = idx >> 5, i2 = idx & 31;
        float freq = powf(10000.0f, -(2.0f * (float)i2) / 64.0f);
        float ang = (float)l * freq;
        g_sin[idx] = sinf(ang);
        g_cos[idx] = cosf(ang);
    }
}

// =============================================================
// Stage 1: proj = x @ W + b, RoPE, write Q/K f16
// 128 threads (4 warps), CTA tile 128x128, warp 64x64, BK=64,
// A double-buffered + B single-buffered (48KB) -> 4 CTA/SM,
// f16 acc, ks-double-buffered frags, swizzled 128B rows.
// =============================================================
#define S1_TILE 16384
#define S1_B_OFF (2 * S1_TILE)              // B buffer after 2 A stages
#define S1_SMEM (3 * S1_TILE)               // 49152 B

__global__ __launch_bounds__(128, 4) void stage1(const float* __restrict__ bias) {
    extern __shared__ char sm1[];
    __shared__ float sBias[128];
    uint32_t base = saddr(sm1);

    int tid = threadIdx.x, warp = tid >> 5, lane = tid & 31;
    int head = blockIdx.x, mblk = blockIdx.y;
    int wm = (warp >> 1) * 64;
    int wn = (warp & 1) * 64;

    if (tid < 128) sBias[tid] = bias[head * 128 + tid];

    const __half* xb = g_x + (size_t)mblk * 128 * DIM;
    const __half* wb = g_Wt + (size_t)head * 128 * DIM;
    int lrow = tid >> 3;
    int lch = (tid & 7) * 16;

    auto issueA = [&](int buf, int t) {
        uint32_t ab = base + buf * S1_TILE;
        const __half* xp = xb + t * 64 + (tid & 7) * 8;
#pragma unroll
        for (int it = 0; it < 8; it++) {
            int row = it * 16 + lrow;
            uint32_t o = row * 128 + lch;
            cpasync16s(ab + SW128(o), xp + (size_t)row * DIM);
        }
        CP_COMMIT;
    };
    auto issueB = [&](int t) {
        uint32_t bb = base + S1_B_OFF;
        const __half* wp = wb + t * 64 + (tid & 7) * 8;
#pragma unroll
        for (int it = 0; it < 8; it++) {
            int row = it * 16 + lrow;
            uint32_t o = row * 128 + lch;
            cpasync16s(bb + SW128(o), wp + (size_t)row * DIM);
        }
        CP_COMMIT;
    };

    uint32_t aOff[4], bOff[4], aXor[4], bXor[4];
#pragma unroll
    for (int mt = 0; mt < 4; mt++) {
        int r = wm + mt * 16 + (lane & 7) + ((lane >> 3) & 1) * 8;
        aXor[mt] = (r & 7) * 16;
        aOff[mt] = r * 128;
    }
#pragma unroll
    for (int np = 0; np < 4; np++) {
        int g = lane >> 3;
        int r = wn + np * 16 + (lane & 7) + (g >> 1) * 8;
        bXor[np] = (r & 7) * 16;
        bOff[np] = r * 128;
    }
    uint32_t aC0 = (lane >> 4) * 16;
    uint32_t bC0 = ((lane >> 3) & 1) * 16;

    unsigned acc[4][8][2];
#pragma unroll
    for (int a = 0; a < 4; a++)
#pragma unroll
        for (int b = 0; b < 8; b++) { acc[a][b][0] = 0u; acc[a][b][1] = 0u; }

    // prologue groups (FIFO): B(0), A(0), A(1)
    issueB(0);
    issueA(0, 0);
    issueA(1, 1);

    unsigned af[2][4][4], bf[2][4][4];

    const int NK = DIM / 64;   // 12
    for (int i = 0; i < NK; i++) {
        // needed now: A(i), B(i). Newest pending group is A(i+1) except last iter.
        if (i == NK - 1) { CP_WAIT(0); } else { CP_WAIT(1); }
        __syncthreads();
        uint32_t ab = base + (i & 1) * S1_TILE;
        uint32_t bb = base + S1_B_OFF;

        // preload ks=0 fragments
#pragma unroll
        for (int mt = 0; mt < 4; mt++)
            ldmx4(af[0][mt], ab + aOff[mt] + (aC0 ^ aXor[mt]));
#pragma unroll
        for (int np = 0; np < 4; np++)
            ldmx4(bf[0][np], bb + bOff[np] + (bC0 ^ bXor[np]));

#pragma unroll
        for (int ks = 0; ks < 4; ks++) {
            int cur = ks & 1, nxt = cur ^ 1;
            if (ks < 3) {
                uint32_t kc = (ks + 1) * 32;
#pragma unroll
                for (int mt = 0; mt < 4; mt++)
                    ldmx4(af[nxt][mt], ab + aOff[mt] + ((kc + aC0) ^ aXor[mt]));
#pragma unroll
                for (int np = 0; np < 4; np++)
                    ldmx4(bf[nxt][np], bb + bOff[np] + ((kc + bC0) ^ bXor[np]));
            }
#pragma unroll
            for (int mt = 0; mt < 4; mt++)
#pragma unroll
                for (int np = 0; np < 4; np++) {
                    mmaf16(acc[mt][2 * np],     af[cur][mt], &bf[cur][np][0]);
                    mmaf16(acc[mt][2 * np + 1], af[cur][mt], &bf[cur][np][2]);
                }
        }
        __syncthreads();   // all reads of A(i)/B(i) done; safe to overwrite
        if (i + 1 < NK) issueB(i + 1);
        if (i + 2 < NK) issueA(i & 1, i + 2);
    }

    // epilogue: bias + RoPE, write Q/K f16
    int gmb = mblk * 128;
#pragma unroll
    for (int mt = 0; mt < 4; mt++) {
#pragma unroll
        for (int nt = 0; nt < 8; nt++) {
            int ncol = wn + nt * 8 + 2 * (lane & 3);
            int rch = ncol & 63;
            int i = rch >> 1;
            bool isQ = ncol < 64;
            float b0 = sBias[ncol], b1 = sBias[ncol + 1];
#pragma unroll
            for (int rr = 0; rr < 2; rr++) {
                int row = wm + mt * 16 + (lane >> 2) + rr * 8;
                int gm = gmb + row;
                int bb2 = gm >> 9;
                int l = gm & 511;
                __half2 h = *reinterpret_cast<__half2*>(&acc[mt][nt][rr]);
                float v0 = __low2float(h) + b0;
                float v1 = __high2float(h) + b1;
                float sn = g_sin[l * 32 + i], cs = g_cos[l * 32 + i];
                float o0 = v0 * cs - v1 * sn;
                float o1 = v1 * cs + v0 * sn;
                size_t off = (((size_t)(bb2 * HEADS + head) * SEQ + l) * HEAD_S + rch);
                __half* dst = (isQ ? g_Q : g_K) + off;
                *(__half2*)dst = __floats2half2_rn(o0, o1);
            }
        }
    }
}

// =============================================================
// Stage 2: per (b,h): full 128x512 strip per CTA (R11/R13 winner, unchanged)
// =============================================================
#define S2_Q_OFF 0
#define S2_K_OFF (128 * 72 * 2)
#define S2_RS_OFF (S2_K_OFF + 512 * 72 * 2)
#define S2_RA_OFF (S2_RS_OFF + 128 * 4)
#define S2_CM_OFF (S2_RA_OFF + 128 * 4)
#define S2_CA_OFF (S2_CM_OFF + 512 * 4)
#define S2_SMEM   (S2_CA_OFF + 512 * 4)     // 97280

__global__ __launch_bounds__(256, 2) void stage2(const float* __restrict__ mask,
                                                 float* __restrict__ out) {
    extern __shared__ char sm2[];
    __half* sQ = (__half*)(sm2 + S2_Q_OFF);
    __half* sK = (__half*)(sm2 + S2_K_OFF);
    float* s_rs = (float*)(sm2 + S2_RS_OFF);
    float* s_ra = (float*)(sm2 + S2_RA_OFF);
    float* s_cm = (float*)(sm2 + S2_CM_OFF);
    float* s_ca = (float*)(sm2 + S2_CA_OFF);

    int mtb = blockIdx.x, bh = blockIdx.y;
    int b = bh / HEADS;
    int tid = threadIdx.x, warp = tid >> 5, lane = tid & 31;
    int wm = (warp >> 1) * 32;
    int wn = (warp & 1) * 64;

    const __half* Qb = g_Q + (size_t)bh * SEQ * HEAD_S + (size_t)mtb * 128 * HEAD_S;
    const __half* Kb = g_K + (size_t)bh * SEQ * HEAD_S;

    int lrow = tid >> 3, lkk = (tid & 7) * 8;
#pragma unroll
    for (int it = 0; it < 4; it++) {
        int row = it * 32 + lrow;
        cpasync16s(saddr(&sQ[row * 72 + lkk]), Qb + (size_t)row * HEAD_S + lkk);
    }
#pragma unroll
    for (int it = 0; it < 16; it++) {
        int row = it * 32 + lrow;
        cpasync16s(saddr(&sK[row * 72 + lkk]), Kb + (size_t)row * HEAD_S + lkk);
    }
    CP_COMMIT;

    const float* mrow = mask + (size_t)b * SEQ;
    if (tid < 128) {
        float m2 = mrow[mtb * 128 + tid];
        s_rs[tid] = m2 * 0.125f;
        s_ra[tid] = (1.0f - m2) * (-NEG8);
    }
#pragma unroll
    for (int q = 0; q < 2; q++) {
        int cidx = q * 256 + tid;
        float m3 = mrow[cidx];
        s_cm[cidx] = m3;
        s_ca[cidx] = (1.0f - m3) * (-NEG8);
    }
    CP_WAIT(0);
    __syncthreads();

    float* ob = out + (size_t)bh * (SEQ * SEQ);

    for (int ntb = 0; ntb < 4; ntb++) {
        float acc[2][8][4];
#pragma unroll
        for (int a = 0; a < 2; a++)
#pragma unroll
            for (int c = 0; c < 8; c++)
#pragma unroll
                for (int d = 0; d < 4; d++) acc[a][c][d] = 0.0f;

#pragma unroll
        for (int ks = 0; ks < 4; ks++) {
            int kb = ks * 16;
            unsigned a[2][4], bf[4][4];
#pragma unroll
            for (int mt = 0; mt < 2; mt++) {
                int r = wm + mt * 16 + (lane & 7) + ((lane >> 3) & 1) * 8;
                int c = kb + (lane >> 4) * 8;
                ldmx4(a[mt], saddr(&sQ[r * 72 + c]));
            }
#pragma unroll
            for (int np = 0; np < 4; np++) {
                int g = lane >> 3;
                int r = ntb * 128 + wn + np * 16 + (lane & 7) + (g >> 1) * 8;
                int c = kb + (g & 1) * 8;
                ldmx4(bf[np], saddr(&sK[r * 72 + c]));
            }
#pragma unroll
            for (int mt = 0; mt < 2; mt++)
#pragma unroll
                for (int np = 0; np < 4; np++) {
                    mmaf32(acc[mt][2 * np], a[mt], &bf[np][0]);
                    mmaf32(acc[mt][2 * np + 1], a[mt], &bf[np][2]);
                }
        }

#pragma unroll
        for (int mt = 0; mt < 2; mt++) {
#pragma unroll
            for (int rr = 0; rr < 2; rr++) {
                int rl = wm + mt * 16 + (lane >> 2) + rr * 8;
                int row = mtb * 128 + rl;
                float rs = s_rs[rl], ra = s_ra[rl];
#pragma unroll
                for (int nt = 0; nt < 8; nt++) {
                    int col = ntb * 128 + wn + nt * 8 + 2 * (lane & 3);
                    int cl = col & 511;
                    float v0 = (acc[mt][nt][rr * 2 + 0] * rs + ra) * s_cm[cl] + s_ca[cl];
                    float v1 = (acc[mt][nt][rr * 2 + 1] * rs + ra) * s_cm[cl + 1] + s_ca[cl + 1];
                    if (row > col)     v0 -= NEG8;
                    if (row > col + 1) v1 -= NEG8;
                    __stcs((float2*)&ob[(size_t)row * SEQ + col], make_float2(v0, v1));
                }
            }
        }
    }
}

extern "C" void kernel_launch(void* const* d_in, const int* in_sizes, int n_in,
                              void* d_out, int out_size) {
    const float* x    = (const float*)d_in[0];
    const float* mask = (const float*)d_in[1];
    const float* W    = (const float*)d_in[2];
    const float* bias = (const float*)d_in[3];
    float* out = (float*)d_out;

    static bool init_done = false;
    if (!init_done) {
        cudaFuncSetAttribute(stage1, cudaFuncAttributeMaxDynamicSharedMemorySize, S1_SMEM);
        cudaFuncSetAttribute(stage2, cudaFuncAttributeMaxDynamicSharedMemorySize, S2_SMEM);
        init_done = true;
    }

    prep<<<PREP_XBLK + PREP_WBLK + PREP_RBLK, 256>>>(x, W);
    stage1<<<dim3(HEADS, MROWS / 128), 128, S1_SMEM>>>(bias);
    stage2<<<dim3(4, BATCH * HEADS), 256, S2_SMEM>>>(mask, out);
}

// round 16
// speedup vs baseline: 1.1537x; 1.0183x over previous
#include <cuda_runtime.h>
#include <cuda_fp16.h>
#include <cstdint>

#define HEADS 12
#define HEAD_S 64
#define BATCH 32
#define SEQ 512
#define DIM 768
#define NPROJ (HEADS * HEAD_S * 2)   // 1536
#define MROWS (BATCH * SEQ)          // 16384
#define NEGC 1000000000000.0f
#define NEG8 (NEGC * 0.125f)

// -------- scratch (device globals; no allocation allowed) --------
__device__ __half g_x[(size_t)MROWS * DIM];
__device__ __half g_Wt[NPROJ * DIM];
__device__ __half g_Q[(size_t)BATCH * HEADS * SEQ * HEAD_S];
__device__ __half g_K[(size_t)BATCH * HEADS * SEQ * HEAD_S];
__device__ float g_sin[SEQ * 32];
__device__ float g_cos[SEQ * 32];

// -------- helpers --------
#define SW128(o) ((o) ^ (((o) >> 3) & 0x70))    // 128B-row xor swizzle

__device__ __forceinline__ uint32_t saddr(const void* p) {
    return (uint32_t)__cvta_generic_to_shared(p);
}
__device__ __forceinline__ unsigned pkh(float a, float b) {
    __half2 h = __floats2half2_rn(a, b);
    return *reinterpret_cast<unsigned*>(&h);
}
__device__ __forceinline__ void cpasync16s(uint32_t s, const void* gmem) {
    asm volatile("cp.async.cg.shared.global [%0], [%1], 16;" :: "r"(s), "l"(gmem));
}
#define CP_COMMIT asm volatile("cp.async.commit_group;")
#define CP_WAIT(n) asm volatile("cp.async.wait_group %0;" :: "n"(n))

__device__ __forceinline__ void ldmx4(unsigned* r, uint32_t addr) {
    asm volatile("ldmatrix.sync.aligned.m8n8.x4.shared.b16 {%0,%1,%2,%3},[%4];"
                 : "=r"(r[0]), "=r"(r[1]), "=r"(r[2]), "=r"(r[3]) : "r"(addr));
}
// f16-acc MMA
__device__ __forceinline__ void mmaf16(unsigned* c, const unsigned* a, const unsigned* b) {
    asm volatile(
        "mma.sync.aligned.m16n8k16.row.col.f16.f16.f16.f16 "
        "{%0,%1},{%2,%3,%4,%5},{%6,%7},{%0,%1};"
        : "+r"(c[0]), "+r"(c[1])
        : "r"(a[0]), "r"(a[1]), "r"(a[2]), "r"(a[3]), "r"(b[0]), "r"(b[1]));
}

// =============================================================
// Fused prep: x->f16 (0..6143), W transpose->f16 (6144..7295), rope (7296..7359)
// =============================================================
#define PREP_XBLK 6144
#define PREP_WBLK 1152
#define PREP_RBLK 64
__global__ __launch_bounds__(256) void prep(const float* __restrict__ x,
                                            const float* __restrict__ W) {
    __shared__ float t[32][33];
    int bid = blockIdx.x, tid = threadIdx.x;
    if (bid < PREP_XBLK) {
        size_t i = ((size_t)bid * 256 + tid) * 8;
        const float4* p = (const float4*)(x + i);
        float4 u = p[0], v = p[1];
        uint4 w;
        w.x = pkh(u.x, u.y); w.y = pkh(u.z, u.w);
        w.z = pkh(v.x, v.y); w.w = pkh(v.z, v.w);
        *(uint4*)&g_x[i] = w;
    } else if (bid < PREP_XBLK + PREP_WBLK) {
        int tile = bid - PREP_XBLK;
        int nt = (tile % 48) * 32, kt = (tile / 48) * 32;
        int tx = tid & 31, ty = tid >> 5;
        for (int i2 = ty; i2 < 32; i2 += 8)
            t[i2][tx] = W[(size_t)(kt + i2) * NPROJ + nt + tx];
        __syncthreads();
        for (int i2 = ty; i2 < 32; i2 += 8)
            g_Wt[(size_t)(nt + i2) * DIM + kt + tx] = __float2half(t[tx][i2]);
    } else {
        int idx = (bid - PREP_XBLK - PREP_WBLK) * 256 + tid;  // < 16384
        int l = idx >> 5, i2 = idx & 31;
        float freq = powf(10000.0f, -(2.0f * (float)i2) / 64.0f);
        float ang = (float)l * freq;
        g_sin[idx] = sinf(ang);
        g_cos[idx] = cosf(ang);
    }
}

// =============================================================
// Stage 1 (R15 winner, unchanged): 128 threads, warp 64x64, BK=64,
// A double + B single buffer (48KB) -> 4 CTA/SM, f16 acc
// =============================================================
#define S1_TILE 16384
#define S1_B_OFF (2 * S1_TILE)
#define S1_SMEM (3 * S1_TILE)               // 49152 B

__global__ __launch_bounds__(128, 4) void stage1(const float* __restrict__ bias) {
    extern __shared__ char sm1[];
    __shared__ float sBias[128];
    uint32_t base = saddr(sm1);

    int tid = threadIdx.x, warp = tid >> 5, lane = tid & 31;
    int head = blockIdx.x, mblk = blockIdx.y;
    int wm = (warp >> 1) * 64;
    int wn = (warp & 1) * 64;

    if (tid < 128) sBias[tid] = bias[head * 128 + tid];

    const __half* xb = g_x + (size_t)mblk * 128 * DIM;
    const __half* wb = g_Wt + (size_t)head * 128 * DIM;
    int lrow = tid >> 3;
    int lch = (tid & 7) * 16;

    auto issueA = [&](int buf, int t) {
        uint32_t ab = base + buf * S1_TILE;
        const __half* xp = xb + t * 64 + (tid & 7) * 8;
#pragma unroll
        for (int it = 0; it < 8; it++) {
            int row = it * 16 + lrow;
            uint32_t o = row * 128 + lch;
            cpasync16s(ab + SW128(o), xp + (size_t)row * DIM);
        }
        CP_COMMIT;
    };
    auto issueB = [&](int t) {
        uint32_t bb = base + S1_B_OFF;
        const __half* wp = wb + t * 64 + (tid & 7) * 8;
#pragma unroll
        for (int it = 0; it < 8; it++) {
            int row = it * 16 + lrow;
            uint32_t o = row * 128 + lch;
            cpasync16s(bb + SW128(o), wp + (size_t)row * DIM);
        }
        CP_COMMIT;
    };

    uint32_t aOff[4], bOff[4], aXor[4], bXor[4];
#pragma unroll
    for (int mt = 0; mt < 4; mt++) {
        int r = wm + mt * 16 + (lane & 7) + ((lane >> 3) & 1) * 8;
        aXor[mt] = (r & 7) * 16;
        aOff[mt] = r * 128;
    }
#pragma unroll
    for (int np = 0; np < 4; np++) {
        int g = lane >> 3;
        int r = wn + np * 16 + (lane & 7) + (g >> 1) * 8;
        bXor[np] = (r & 7) * 16;
        bOff[np] = r * 128;
    }
    uint32_t aC0 = (lane >> 4) * 16;
    uint32_t bC0 = ((lane >> 3) & 1) * 16;

    unsigned acc[4][8][2];
#pragma unroll
    for (int a = 0; a < 4; a++)
#pragma unroll
        for (int b = 0; b < 8; b++) { acc[a][b][0] = 0u; acc[a][b][1] = 0u; }

    issueB(0);
    issueA(0, 0);
    issueA(1, 1);

    unsigned af[2][4][4], bf[2][4][4];

    const int NK = DIM / 64;   // 12
    for (int i = 0; i < NK; i++) {
        if (i == NK - 1) { CP_WAIT(0); } else { CP_WAIT(1); }
        __syncthreads();
        uint32_t ab = base + (i & 1) * S1_TILE;
        uint32_t bb = base + S1_B_OFF;

#pragma unroll
        for (int mt = 0; mt < 4; mt++)
            ldmx4(af[0][mt], ab + aOff[mt] + (aC0 ^ aXor[mt]));
#pragma unroll
        for (int np = 0; np < 4; np++)
            ldmx4(bf[0][np], bb + bOff[np] + (bC0 ^ bXor[np]));

#pragma unroll
        for (int ks = 0; ks < 4; ks++) {
            int cur = ks & 1, nxt = cur ^ 1;
            if (ks < 3) {
                uint32_t kc = (ks + 1) * 32;
#pragma unroll
                for (int mt = 0; mt < 4; mt++)
                    ldmx4(af[nxt][mt], ab + aOff[mt] + ((kc + aC0) ^ aXor[mt]));
#pragma unroll
                for (int np = 0; np < 4; np++)
                    ldmx4(bf[nxt][np], bb + bOff[np] + ((kc + bC0) ^ bXor[np]));
            }
#pragma unroll
            for (int mt = 0; mt < 4; mt++)
#pragma unroll
                for (int np = 0; np < 4; np++) {
                    mmaf16(acc[mt][2 * np],     af[cur][mt], &bf[cur][np][0]);
                    mmaf16(acc[mt][2 * np + 1], af[cur][mt], &bf[cur][np][2]);
                }
        }
        __syncthreads();
        if (i + 1 < NK) issueB(i + 1);
        if (i + 2 < NK) issueA(i & 1, i + 2);
    }

    int gmb = mblk * 128;
#pragma unroll
    for (int mt = 0; mt < 4; mt++) {
#pragma unroll
        for (int nt = 0; nt < 8; nt++) {
            int ncol = wn + nt * 8 + 2 * (lane & 3);
            int rch = ncol & 63;
            int i = rch >> 1;
            bool isQ = ncol < 64;
            float b0 = sBias[ncol], b1 = sBias[ncol + 1];
#pragma unroll
            for (int rr = 0; rr < 2; rr++) {
                int row = wm + mt * 16 + (lane >> 2) + rr * 8;
                int gm = gmb + row;
                int bb2 = gm >> 9;
                int l = gm & 511;
                __half2 h = *reinterpret_cast<__half2*>(&acc[mt][nt][rr]);
                float v0 = __low2float(h) + b0;
                float v1 = __high2float(h) + b1;
                float sn = g_sin[l * 32 + i], cs = g_cos[l * 32 + i];
                float o0 = v0 * cs - v1 * sn;
                float o1 = v1 * cs + v0 * sn;
                size_t off = (((size_t)(bb2 * HEADS + head) * SEQ + l) * HEAD_S + rch);
                __half* dst = (isQ ? g_Q : g_K) + off;
                *(__half2*)dst = __floats2half2_rn(o0, o1);
            }
        }
    }
}

// =============================================================
// Stage 2 v2: 128 threads, fat 64x64 warps, f16 acc.
// Per CTA: Q tile 128x64 (16KB swizzled) + K half-strip 256x64 (32KB)
// + masks ~3KB = ~51KB -> 4 CTA/SM.
// grid (8, 384): blockIdx.x = mtb*2 + nhalf, y = bh
// =============================================================
#define T2_Q   0
#define T2_K   16384
#define T2_RS  (T2_K + 32768)        // 49152
#define T2_RA  (T2_RS + 512)
#define T2_CM  (T2_RA + 512)
#define T2_CA  (T2_CM + 1024)
#define T2_SMEM (T2_CA + 1024)       // 52224

__global__ __launch_bounds__(128, 4) void stage2(const float* __restrict__ mask,
                                                 float* __restrict__ out) {
    extern __shared__ char sm2[];
    uint32_t base = saddr(sm2);
    float* s_rs = (float*)(sm2 + T2_RS);
    float* s_ra = (float*)(sm2 + T2_RA);
    float* s_cm = (float*)(sm2 + T2_CM);
    float* s_ca = (float*)(sm2 + T2_CA);

    int mtb = blockIdx.x >> 1, nh = blockIdx.x & 1;
    int bh = blockIdx.y;
    int b = bh / HEADS;
    int tid = threadIdx.x, warp = tid >> 5, lane = tid & 31;
    int wm = (warp >> 1) * 64;
    int wn = (warp & 1) * 64;

    const __half* Qb = g_Q + (size_t)bh * SEQ * HEAD_S + (size_t)mtb * 128 * HEAD_S;
    const __half* Kb = g_K + (size_t)bh * SEQ * HEAD_S + (size_t)nh * 256 * HEAD_S;

    int lrow = tid >> 3;
    int lch = (tid & 7) * 16;
    int lel = (tid & 7) * 8;

    // Q: 128 rows x 128B
#pragma unroll
    for (int it = 0; it < 8; it++) {
        int row = it * 16 + lrow;
        uint32_t o = row * 128 + lch;
        cpasync16s(base + T2_Q + SW128(o), Qb + (size_t)row * HEAD_S + lel);
    }
    // K half-strip: 256 rows x 128B
#pragma unroll
    for (int it = 0; it < 16; it++) {
        int row = it * 16 + lrow;
        uint32_t o = row * 128 + lch;
        cpasync16s(base + T2_K + SW128(o), Kb + (size_t)row * HEAD_S + lel);
    }
    CP_COMMIT;

    // mask precompute (overlaps loads)
    const float* mrow = mask + (size_t)b * SEQ;
    {
        float m2 = mrow[mtb * 128 + tid];
        s_rs[tid] = m2 * 0.125f;
        s_ra[tid] = (1.0f - m2) * (-NEG8);
#pragma unroll
        for (int q = 0; q < 2; q++) {
            int idx = q * 128 + tid;
            float m3 = mrow[nh * 256 + idx];
            s_cm[idx] = m3;
            s_ca[idx] = (1.0f - m3) * (-NEG8);
        }
    }

    // fragment address precompute (same scheme as stage1)
    uint32_t aOff[4], bOff[4], aXor[4], bXor[4];
#pragma unroll
    for (int mt = 0; mt < 4; mt++) {
        int r = wm + mt * 16 + (lane & 7) + ((lane >> 3) & 1) * 8;
        aXor[mt] = (r & 7) * 16;
        aOff[mt] = r * 128;
    }
#pragma unroll
    for (int np = 0; np < 4; np++) {
        int g = lane >> 3;
        int r = wn + np * 16 + (lane & 7) + (g >> 1) * 8;
        bXor[np] = (r & 7) * 16;
        bOff[np] = r * 128;
    }
    uint32_t aC0 = (lane >> 4) * 16;
    uint32_t bC0 = ((lane >> 3) & 1) * 16;

    CP_WAIT(0);
    __syncthreads();

    float* ob = out + (size_t)bh * (SEQ * SEQ);

#pragma unroll
    for (int ntb = 0; ntb < 2; ntb++) {
        uint32_t kbase = base + T2_K + ntb * 16384;

        unsigned acc[4][8][2];
#pragma unroll
        for (int a = 0; a < 4; a++)
#pragma unroll
            for (int c = 0; c < 8; c++) { acc[a][c][0] = 0u; acc[a][c][1] = 0u; }

#pragma unroll
        for (int ks = 0; ks < 4; ks++) {
            uint32_t kc = ks * 32;
            unsigned a[4][4], bf[4][4];
#pragma unroll
            for (int mt = 0; mt < 4; mt++)
                ldmx4(a[mt], base + T2_Q + aOff[mt] + ((kc + aC0) ^ aXor[mt]));
#pragma unroll
            for (int np = 0; np < 4; np++)
                ldmx4(bf[np], kbase + bOff[np] + ((kc + bC0) ^ bXor[np]));
#pragma unroll
            for (int mt = 0; mt < 4; mt++)
#pragma unroll
                for (int np = 0; np < 4; np++) {
                    mmaf16(acc[mt][2 * np],     a[mt], &bf[np][0]);
                    mmaf16(acc[mt][2 * np + 1], a[mt], &bf[np][2]);
                }
        }

        // epilogue
#pragma unroll
        for (int mt = 0; mt < 4; mt++) {
#pragma unroll
            for (int rr = 0; rr < 2; rr++) {
                int rl = wm + mt * 16 + (lane >> 2) + rr * 8;
                int row = mtb * 128 + rl;
                float rs = s_rs[rl], ra = s_ra[rl];
#pragma unroll
                for (int nt = 0; nt < 8; nt++) {
                    int cloc = ntb * 128 + wn + nt * 8 + 2 * (lane & 3);
                    int col = nh * 256 + cloc;
                    __half2 h = *reinterpret_cast<__half2*>(&acc[mt][nt][rr]);
                    float v0 = (__low2float(h)  * rs + ra) * s_cm[cloc] + s_ca[cloc];
                    float v1 = (__high2float(h) * rs + ra) * s_cm[cloc + 1] + s_ca[cloc + 1];
                    if (row > col)     v0 -= NEG8;
                    if (row > col + 1) v1 -= NEG8;
                    __stcs((float2*)&ob[(size_t)row * SEQ + col], make_float2(v0, v1));
                }
            }
        }
    }
}

extern "C" void kernel_launch(void* const* d_in, const int* in_sizes, int n_in,
                              void* d_out, int out_size) {
    const float* x    = (const float*)d_in[0];
    const float* mask = (const float*)d_in[1];
    const float* W    = (const float*)d_in[2];
    const float* bias = (const float*)d_in[3];
    float* out = (float*)d_out;

    static bool init_done = false;
    if (!init_done) {
        cudaFuncSetAttribute(stage1, cudaFuncAttributeMaxDynamicSharedMemorySize, S1_SMEM);
        cudaFuncSetAttribute(stage2, cudaFuncAttributeMaxDynamicSharedMemorySize, T2_SMEM);
        init_done = true;
    }

    prep<<<PREP_XBLK + PREP_WBLK + PREP_RBLK, 256>>>(x, W);
    stage1<<<dim3(HEADS, MROWS / 128), 128, S1_SMEM>>>(bias);
    stage2<<<dim3(8, BATCH * HEADS), 128, T2_SMEM>>>(mask, out);
}